// round 16
// baseline (speedup 1.0000x reference)
#include <cuda_runtime.h>
#include <cuda_bf16.h>
#include <cstddef>
#include <cstdint>

typedef unsigned long long ull;

// ---------------- problem constants ----------------
constexpr int Bc  = 256;
constexpr int Tc  = 512;
constexpr int Ic  = 64;
constexpr int Hc  = 512;
constexpr int Gc  = 4 * Hc;      // 2048
constexpr int HOR = 30;
constexpr int NQc = 3;
constexpr int NBLK = 128;

// ---------------- device scratch ----------------
__device__ float g_pre[(size_t)Bc * Tc * Gc];                // (B*T,2048) pair-permuted L0 pre-projections
__device__ __nv_bfloat16 g_xb[(size_t)Bc * Tc * Ic];         // x in bf16
__device__ __nv_bfloat16 g_hb0[(size_t)Bc * Tc * Hc];        // layer-0 h history (B,T,512)
__device__ __nv_bfloat16 g_hb1[(size_t)Bc * Tc * Hc];        // layer-1 h history
__device__ __nv_bfloat16 g_encproj[(size_t)Bc * Tc * Hc];    // bf16 enc_out @ attn_W^T
__device__ float g_part[(size_t)64 * 128 * 64];              // per (mt,ut): 128 rows x 64 gate-cols fp32 partial

// encoder weights bf16, pair-permuted rows (n<1024: (i,f) of unit n>>1; n>=1024: (g,o))
__device__ __nv_bfloat16 g_Wih0b[Gc * Ic];
__device__ __nv_bfloat16 g_Whh0b[Gc * Hc];
__device__ __nv_bfloat16 g_Wih1b[Gc * Hc];
__device__ __nv_bfloat16 g_Whh1b[Gc * Hc];
__device__ __nv_bfloat16 g_attnWb[Hc * Hc];                  // plain layout bf16
__device__ float g_bE0p2[Gc];
__device__ float g_bE1p2[Gc];

// decoder weights fp32, permutation gp = jh*4+q
__device__ float g_dwrestp[Gc * Hc];
__device__ float g_dWhh0p[Gc * Hc];
__device__ float g_dWih1p[Gc * Hc];
__device__ float g_dWhh1p[Gc * Hc];
__device__ float g_dwcol0p[Gc];
__device__ float g_bD0p[Gc];
__device__ float g_bD1p[Gc];

__device__ float g_c1[Bc * Hc];
__device__ float g_hd0[Bc * Hc];
__device__ float g_hd1[Bc * Hc];
__device__ float g_cd0[Bc * Hc];
__device__ float g_cd1[Bc * Hc];
__device__ float g_cdump[Bc * Hc];
__device__ float g_h0tmp[Bc * Hc];
__device__ float g_ctx[Bc * Hc];
__device__ float g_decproj[Bc * Hc];
__device__ float g_energy[Bc * Tc];
__device__ float g_dinp[Bc];

// encoder pipeline counters (zeroed by prep each run): [mt] per layer
__device__ unsigned g_cntA[2];
__device__ unsigned g_cntB[2];
__device__ unsigned g_fP[64];   // per-block partial flags (producer: L0 block lb)

// decoder global barrier (self-resetting)
__device__ unsigned g_arrive = 0;
__device__ unsigned g_release = 0;

__device__ __forceinline__ void grid_sync() {
    __syncthreads();
    if (threadIdx.x == 0) {
        __threadfence();
        unsigned prev = *((volatile unsigned*)&g_release);
        unsigned a = atomicAdd(&g_arrive, 1u);
        if (a == gridDim.x - 1u) {
            atomicExch(&g_arrive, 0u);
            __threadfence();
            atomicExch(&g_release, prev + 1u);
        } else {
            while (*((volatile unsigned*)&g_release) == prev) __nanosleep(64);
        }
        __threadfence();
    }
    __syncthreads();
}

// ---------------- math helpers ----------------
__device__ __forceinline__ float sigf(float x) {
    return __fdividef(1.0f, 1.0f + __expf(-x));
}
__device__ __forceinline__ float tanhfast(float x) {
    return 1.0f - __fdividef(2.0f, __expf(2.0f * x) + 1.0f);
}
__device__ __forceinline__ float tanh_hw(float x) {
    float y; asm("tanh.approx.f32 %0, %1;" : "=f"(y) : "f"(x)); return y;
}
__device__ __forceinline__ ull pack2(float lo, float hi) {
    ull r; asm("mov.b64 %0, {%1, %2};" : "=l"(r) : "f"(lo), "f"(hi)); return r;
}
__device__ __forceinline__ float2 unpack2(ull v) {
    float2 f; asm("mov.b64 {%0, %1}, %2;" : "=f"(f.x), "=f"(f.y) : "l"(v)); return f;
}
__device__ __forceinline__ void fma2(ull& d, ull a, ull b) {
    asm("fma.rn.f32x2 %0, %1, %2, %0;" : "+l"(d) : "l"(a), "l"(b));
}
__device__ __forceinline__ void red_release_add(unsigned* p, unsigned v) {
    asm volatile("red.release.gpu.global.add.u32 [%0], %1;" :: "l"(p), "r"(v) : "memory");
}

// ---------------- async copy helpers ----------------
__device__ __forceinline__ void cp_async16(uint32_t dst, const void* src) {
    asm volatile("cp.async.cg.shared.global [%0], [%1], 16;" :: "r"(dst), "l"(src));
}
__device__ __forceinline__ void cp_commit() {
    asm volatile("cp.async.commit_group;");
}
template<int N>
__device__ __forceinline__ void cp_wait() {
    asm volatile("cp.async.wait_group %0;" :: "n"(N));
}

// ---------------- tensor-core helpers ----------------
__device__ __forceinline__ void ldsm_x4(uint32_t (&r)[4], uint32_t addr) {
    asm volatile("ldmatrix.sync.aligned.m8n8.x4.shared.b16 {%0,%1,%2,%3}, [%4];"
        : "=r"(r[0]), "=r"(r[1]), "=r"(r[2]), "=r"(r[3]) : "r"(addr));
}
__device__ __forceinline__ void ldsm_x2(uint32_t (&r)[2], uint32_t addr) {
    asm volatile("ldmatrix.sync.aligned.m8n8.x2.shared.b16 {%0,%1}, [%2];"
        : "=r"(r[0]), "=r"(r[1]) : "r"(addr));
}
__device__ __forceinline__ void mma16816(float (&d)[4], const uint32_t (&a)[4], const uint32_t (&b)[2]) {
    asm volatile("mma.sync.aligned.m16n8k16.row.col.f32.bf16.bf16.f32 "
        "{%0,%1,%2,%3}, {%4,%5,%6,%7}, {%8,%9}, {%0,%1,%2,%3};"
        : "+f"(d[0]), "+f"(d[1]), "+f"(d[2]), "+f"(d[3])
        : "r"(a[0]), "r"(a[1]), "r"(a[2]), "r"(a[3]), "r"(b[0]), "r"(b[1]));
}

// ---------------- prep ----------------
__global__ void prep_kernel(const float* __restrict__ x,
    const float* __restrict__ eWih0, const float* __restrict__ eWhh0,
    const float* __restrict__ ebih0, const float* __restrict__ ebhh0,
    const float* __restrict__ eWih1, const float* __restrict__ eWhh1,
    const float* __restrict__ ebih1, const float* __restrict__ ebhh1,
    const float* __restrict__ dWih0, const float* __restrict__ dWhh0,
    const float* __restrict__ dbih0, const float* __restrict__ dbhh0,
    const float* __restrict__ dWih1, const float* __restrict__ dWhh1,
    const float* __restrict__ dbih1, const float* __restrict__ dbhh1,
    const float* __restrict__ attnW)
{
    int idx = blockIdx.x * 256 + threadIdx.x;   // grid covers B*T*I = 8,388,608

    if (idx < Bc * Tc * Ic) g_xb[idx] = __float2bfloat16_rn(x[idx]);

    if (idx < Gc * Hc) {
        int n = idx / Hc;
        int k = idx - n * Hc;

        // decoder: permutation gp = jh*4+q (fp32)
        int g_old = (n & 3) * Hc + (n >> 2);
        size_t so = (size_t)g_old * Hc + k;
        g_dWhh0p[idx] = dWhh0[so];
        g_dWih1p[idx] = dWih1[so];
        g_dWhh1p[idx] = dWhh1[so];
        g_dwrestp[idx] = dWih0[(size_t)g_old * (Hc + 1) + 1 + k];
        if (k == 0) {
            g_dwcol0p[n] = dWih0[(size_t)g_old * (Hc + 1)];
            g_bD0p[n] = dbih0[g_old] + dbhh0[g_old];
            g_bD1p[n] = dbih1[g_old] + dbhh1[g_old];
        }

        // encoder: pair permutation, plain bf16
        int q  = (n < 1024) ? (n & 1) : 2 + (n & 1);
        int jh = ((n < 1024) ? n : n - 1024) >> 1;
        int g2 = q * Hc + jh;
        size_t s2 = (size_t)g2 * Hc + k;
        g_Whh0b[idx] = __float2bfloat16_rn(eWhh0[s2]);
        g_Wih1b[idx] = __float2bfloat16_rn(eWih1[s2]);
        g_Whh1b[idx] = __float2bfloat16_rn(eWhh1[s2]);
        if (k < Ic) g_Wih0b[(size_t)n * Ic + k] = __float2bfloat16_rn(eWih0[(size_t)g2 * Ic + k]);
        if (k == 0) {
            g_bE0p2[n] = ebih0[g2] + ebhh0[g2];
            g_bE1p2[n] = ebih1[g2] + ebhh1[g2];
        }
    }

    if (idx < Hc * Hc) g_attnWb[idx] = __float2bfloat16_rn(attnW[idx]);
    if (idx < 2) { g_cntA[idx] = 0u; g_cntB[idx] = 0u; }
    if (idx < 64) g_fP[idx] = 0u;
    if (idx < Bc) g_dinp[idx] = x[(size_t)idx * Tc * Ic + (size_t)(Tc - 1) * Ic];
}

// ---------------- HMMA streaming core (one-shot GEMMs, 256 threads) ----------------
template<int MF>
__device__ __forceinline__ void hmma_core(
    const __nv_bfloat16* __restrict__ A, size_t lda,
    const __nv_bfloat16* __restrict__ Wif, const __nv_bfloat16* __restrict__ Wgo,
    size_t ldw, int kchunks,
    float (&aif)[MF][4], float (&ago)[MF][4],
    char* sA, char* sW, int tid, int wid, int lane)
{
    uint32_t sAb = (uint32_t)__cvta_generic_to_shared(sA);
    uint32_t sWb = (uint32_t)__cvta_generic_to_shared(sW);
    const int lr = lane & 15, hb = lane >> 4;
    const int nb = wid * 8 + (lane & 7), bsel = (lane >> 3) & 1;

    for (int kc = 0; kc < kchunks; ++kc) {
        __syncthreads();
#pragma unroll
        for (int j = 0; j < MF / 2; ++j) {
            int i = tid + j * 256;
            int r = i >> 3, c = i & 7;
            *(uint4*)(sA + ((r * 8 + (c ^ (r & 7))) << 4)) =
                *(const uint4*)(A + (size_t)r * lda + kc * 64 + c * 8);
        }
#pragma unroll
        for (int j = 0; j < 2; ++j) {
            int i = tid + j * 256;
            int r = i >> 3, c = i & 7;
            *(uint4*)(sW + ((r * 8 + (c ^ (r & 7))) << 4)) =
                *(const uint4*)(Wif + (size_t)r * ldw + kc * 64 + c * 8);
            *(uint4*)(sW + 8192 + ((r * 8 + (c ^ (r & 7))) << 4)) =
                *(const uint4*)(Wgo + (size_t)r * ldw + kc * 64 + c * 8);
        }
        __syncthreads();
#pragma unroll
        for (int s = 0; s < 4; ++s) {
            uint32_t b_if[2], b_go[2];
            int cb = 2 * s + bsel;
            uint32_t boff = (uint32_t)((nb * 8 + (cb ^ (nb & 7))) << 4);
            ldsm_x2(b_if, sWb + boff);
            ldsm_x2(b_go, sWb + 8192u + boff);
            int ca = 2 * s + hb;
#pragma unroll
            for (int mf = 0; mf < MF; ++mf) {
                uint32_t a[4];
                int row = mf * 16 + lr;
                ldsm_x4(a, sAb + (uint32_t)((row * 8 + (ca ^ (lr & 7))) << 4));
                mma16816(aif[mf], a, b_if);
                mma16816(ago[mf], a, b_go);
            }
        }
    }
}

// one-shot bf16 GEMM into pair-permuted gate layout (for P0), fp32 out
__global__ void __launch_bounds__(256) gemm_bf16pair(
    const __nv_bfloat16* __restrict__ A, size_t lda,
    const __nv_bfloat16* __restrict__ Ws, size_t ldw, int K,
    float* __restrict__ C, size_t ldc)
{
    constexpr int MF = 4;
    __shared__ __align__(16) char sA[MF * 16 * 128];
    __shared__ __align__(16) char sW[128 * 128];
    const int tid = threadIdx.x, wid = tid >> 5, lane = tid & 31;
    const size_t m0 = (size_t)blockIdx.x * (MF * 16);
    const int ny = blockIdx.y;

    float aif[MF][4], ago[MF][4];
#pragma unroll
    for (int i = 0; i < MF; ++i)
#pragma unroll
        for (int j = 0; j < 4; ++j) { aif[i][j] = 0.f; ago[i][j] = 0.f; }

    hmma_core<MF>(A + m0 * lda, lda,
                  Ws + (size_t)(ny * 64) * ldw,
                  Ws + (size_t)(1024 + ny * 64) * ldw,
                  ldw, K / 64, aif, ago, sA, sW, tid, wid, lane);

    const int local = 2 * (wid * 4 + (lane & 3));
    size_t cif = (size_t)ny * 64 + local;
    size_t cgo = 1024 + (size_t)ny * 64 + local;
    const int r0 = lane >> 2;
#pragma unroll
    for (int mf = 0; mf < MF; ++mf) {
        size_t row = m0 + mf * 16 + r0;
        *(float2*)(C + row * ldc + cif)       = make_float2(aif[mf][0], aif[mf][1]);
        *(float2*)(C + (row + 8) * ldc + cif) = make_float2(aif[mf][2], aif[mf][3]);
        *(float2*)(C + row * ldc + cgo)       = make_float2(ago[mf][0], ago[mf][1]);
        *(float2*)(C + (row + 8) * ldc + cgo) = make_float2(ago[mf][2], ago[mf][3]);
    }
}

// one-shot bf16 GEMM, plain layout, bf16 output (for encproj)
__global__ void __launch_bounds__(256) gemm_bf16pb(
    const __nv_bfloat16* __restrict__ A, size_t lda,
    const __nv_bfloat16* __restrict__ Ws, size_t ldw, int K,
    __nv_bfloat16* __restrict__ C, size_t ldc)
{
    constexpr int MF = 4;
    __shared__ __align__(16) char sA[MF * 16 * 128];
    __shared__ __align__(16) char sW[128 * 128];
    const int tid = threadIdx.x, wid = tid >> 5, lane = tid & 31;
    const size_t m0 = (size_t)blockIdx.x * (MF * 16);
    const int ny = blockIdx.y;

    float acc0[MF][4], acc1[MF][4];
#pragma unroll
    for (int i = 0; i < MF; ++i)
#pragma unroll
        for (int j = 0; j < 4; ++j) { acc0[i][j] = 0.f; acc1[i][j] = 0.f; }

    hmma_core<MF>(A + m0 * lda, lda,
                  Ws + (size_t)(ny * 128) * ldw,
                  Ws + (size_t)(ny * 128 + 64) * ldw,
                  ldw, K / 64, acc0, acc1, sA, sW, tid, wid, lane);

    const int local = 2 * (wid * 4 + (lane & 3));
    size_t c0 = (size_t)ny * 128 + local;
    size_t c1 = (size_t)ny * 128 + 64 + local;
    const int r0 = lane >> 2;
#pragma unroll
    for (int mf = 0; mf < MF; ++mf) {
        size_t row = m0 + mf * 16 + r0;
        *(__nv_bfloat162*)(C + row * ldc + c0) =
            __float22bfloat162_rn(make_float2(acc0[mf][0], acc0[mf][1]));
        *(__nv_bfloat162*)(C + (row + 8) * ldc + c0) =
            __float22bfloat162_rn(make_float2(acc0[mf][2], acc0[mf][3]));
        *(__nv_bfloat162*)(C + row * ldc + c1) =
            __float22bfloat162_rn(make_float2(acc1[mf][0], acc1[mf][1]));
        *(__nv_bfloat162*)(C + (row + 8) * ldc + c1) =
            __float22bfloat162_rn(make_float2(acc1[mf][2], acc1[mf][3]));
    }
}

// ---------------- overlapped dual-layer persistent encoder, partial-offload ----------------
// 128 blocks x 512 threads. bid<64: layer 0; else layer 1. lb = bid&63, mt = lb>>5, ut = lb&31.
// L0 block per step: 8 Whh0 chunks -> publish h0[t] -> wait peers -> 4 Wih1 chunks
//   (k-chunks 0-3 of h0[t]) -> write fp32 partial -> flag fP[lb].
// L1 block per step: 4 Wih1 chunks (4-7) + 8 Whh1 chunks (8-15) -> add partial -> epilogue.
// W resident: L0 subs 0-7 Whh0, 8-11 Wih1[0-3]; L1 subs 0-3 Wih1[4-7], 4-11 Whh1[0-7].
__global__ void __launch_bounds__(512, 1) enc_overlap(
    __nv_bfloat16* __restrict__ hb0, __nv_bfloat16* __restrict__ hb1,
    const __nv_bfloat16* __restrict__ Whh0b,
    const __nv_bfloat16* __restrict__ Wih1b, const __nv_bfloat16* __restrict__ Whh1b,
    const float* __restrict__ pre,
    const float* __restrict__ bE0, const float* __restrict__ bE1,
    unsigned* __restrict__ cntA, unsigned* __restrict__ cntB,
    unsigned* __restrict__ fP, float* __restrict__ part,
    float* __restrict__ c1fin)
{
    extern __shared__ __align__(16) char smem[];   // 12 W subs (96KB) then 4 x 16KB A buffers
    const int tid = threadIdx.x, wid = tid >> 5, lane = tid & 31;
    const bool isL1 = (blockIdx.x >= 64);
    const int lb = blockIdx.x & 63;
    const int mt = lb >> 5, ut = lb & 31;
    const int m0 = mt * 128;
    const int p = wid & 1, mh = wid >> 1;

    // resident W load (12 subs both layers)
    for (int i = tid; i < 12 * 512; i += 512) {
        int sub = i >> 9;
        int rem = i & 511;
        int r = rem >> 3, c8 = rem & 7;
        int grow = (r < 32) ? (ut * 32 + r) : (1024 + ut * 32 + (r - 32));
        const __nv_bfloat16* src;
        if (!isL1) src = (sub < 8) ? (Whh0b + (size_t)grow * 512 + sub * 64 + c8 * 8)
                                   : (Wih1b + (size_t)grow * 512 + (sub - 8) * 64 + c8 * 8);
        else       src = (sub < 4) ? (Wih1b + (size_t)grow * 512 + (sub + 4) * 64 + c8 * 8)
                                   : (Whh1b + (size_t)grow * 512 + (sub - 4) * 64 + c8 * 8);
        *(uint4*)(smem + sub * 8192 + ((r * 8 + (c8 ^ (r & 7))) << 4)) = *(const uint4*)src;
    }

    const float* bias = isL1 ? bE1 : bE0;
    const int u = ut * 16 + p * 8 + (lane & 3);
    float2 bif[2], bgo[2];
#pragma unroll
    for (int nt = 0; nt < 2; ++nt) {
        bif[nt] = *(const float2*)(bias + 2 * (u + nt * 4));
        bgo[nt] = *(const float2*)(bias + 1024 + 2 * (u + nt * 4));
    }
    float creg[4] = {0.f, 0.f, 0.f, 0.f};
    __syncthreads();

    const uint32_t sWb32 = (uint32_t)__cvta_generic_to_shared(smem);
    const uint32_t sAb32 = sWb32 + (uint32_t)(12 * 8192);
    char* sA = smem + 12 * 8192;
    const int r0 = tid >> 2, c20 = (tid & 3) * 2;  // staging: 2 x 16B per thread
    __nv_bfloat16* hout = isL1 ? hb1 : hb0;
    unsigned* mycnt = isL1 ? cntB : cntA;
    float* mypart = part + (size_t)lb * 8192;

    float aif[2][4], ago[2][4];

    for (int t = 0; t < Tc; ++t) {
        // prefetch pre (L0 only)
        float2 pif[4], pgo[4];
        if (!isL1) {
#pragma unroll
            for (int hh = 0; hh < 2; ++hh)
#pragma unroll
                for (int nt = 0; nt < 2; ++nt) {
                    int row = m0 + mh * 16 + (lane >> 2) + hh * 8;
                    const float* Pr = pre + ((size_t)row * Tc + t) * 2048;
                    pif[hh * 2 + nt] = *(const float2*)(Pr + 2 * (u + nt * 4));
                    pgo[hh * 2 + nt] = *(const float2*)(Pr + 1024 + 2 * (u + nt * 4));
                }
        }

#pragma unroll
        for (int nt = 0; nt < 2; ++nt)
#pragma unroll
            for (int j = 0; j < 4; ++j) { aif[nt][j] = 0.f; ago[nt][j] = 0.f; }

        // stage(kc, mode): mode 0 = hb0[t-1] chunk kc; 1 = hb0[t] chunk kc;
        //                  2 = L1 (kc<8: hb0[t] kc; else hb1[t-1] kc-8)
        auto stage = [&](int kc, int mode) {
            const __nv_bfloat16* base;
            if (mode == 0)      base = hb0 + ((size_t)(m0 + r0) * Tc + (t - 1)) * 512 + kc * 64;
            else if (mode == 1) base = hb0 + ((size_t)(m0 + r0) * Tc + t) * 512 + kc * 64;
            else base = (kc < 8) ? (hb0 + ((size_t)(m0 + r0) * Tc + t) * 512 + kc * 64)
                                 : (hb1 + ((size_t)(m0 + r0) * Tc + (t - 1)) * 512 + (kc - 8) * 64);
            uint32_t bufb = sAb32 + (uint32_t)((kc & 3) * 16384);
            cp_async16(bufb + (uint32_t)((r0 * 8 + (c20 ^ (r0 & 7))) << 4), base + c20 * 8);
            cp_async16(bufb + (uint32_t)((r0 * 8 + ((c20 + 1) ^ (r0 & 7))) << 4), base + (c20 + 1) * 8);
        };

        // pipelined chunk range [kc0, kcn); wsub index = kc + wOff
        auto run_chunks = [&](int kc0, int kcn, int wOff, int mode) {
            stage(kc0, mode); cp_commit();
            if (kc0 + 1 < kcn) { stage(kc0 + 1, mode); }
            cp_commit();
            for (int kc = kc0; kc < kcn; ++kc) {
                if (kc + 2 < kcn) stage(kc + 2, mode);
                cp_commit();
                cp_wait<2>();
                __syncthreads();

                uint32_t wsub = sWb32 + (uint32_t)((kc + wOff) * 8192);
                uint32_t asub = sAb32 + (uint32_t)((kc & 3) * 16384);
#pragma unroll
                for (int ks = 0; ks < 4; ++ks) {
                    int cb = 2 * ks + ((lane >> 3) & 1);
                    uint32_t b_if[2][2], b_go[2][2];
#pragma unroll
                    for (int nt = 0; nt < 2; ++nt) {
                        int rb = p * 16 + nt * 8 + (lane & 7);
                        ldsm_x2(b_if[nt], wsub + (uint32_t)((rb * 8 + (cb ^ (rb & 7))) << 4));
                        int rg = rb + 32;
                        ldsm_x2(b_go[nt], wsub + (uint32_t)((rg * 8 + (cb ^ (rg & 7))) << 4));
                    }
                    int ra = mh * 16 + (lane & 15);
                    int ca = 2 * ks + (lane >> 4);
                    uint32_t a[4];
                    ldsm_x4(a, asub + (uint32_t)((ra * 8 + (ca ^ (ra & 7))) << 4));
                    mma16816(aif[0], a, b_if[0]);
                    mma16816(aif[1], a, b_if[1]);
                    mma16816(ago[0], a, b_go[0]);
                    mma16816(ago[1], a, b_go[1]);
                }
            }
        };

        if (isL1) {
            // phase 1: Wih1 . h0[t] chunks 4..7 (W subs 0..3)
            if (tid == 0) {
                unsigned needA = 32u * (unsigned)(t + 1);
                while (*(volatile unsigned*)&cntA[mt] < needA) {}
                __threadfence();
            }
            __syncthreads();
            run_chunks(4, 8, -4, 2);

            // phase 2: Whh1 . h1[t-1] chunks 8..15 (W subs 4..11)
            if (t) {
                if (tid == 0) {
                    unsigned needB = 32u * (unsigned)t;
                    while (*(volatile unsigned*)&cntB[mt] < needB) {}
                    __threadfence();
                }
                __syncthreads();
                run_chunks(8, 16, -4, 2);
            }

            // consume partial from L0 counterpart (Wih1 chunks 0..3)
            if (tid == 0) {
                while (*(volatile unsigned*)&fP[lb] < (unsigned)(t + 1)) {}
                __threadfence();
            }
            __syncthreads();
#pragma unroll
            for (int hh = 0; hh < 2; ++hh)
#pragma unroll
                for (int nt = 0; nt < 2; ++nt) {
                    int rl = mh * 16 + (lane >> 2) + hh * 8;
                    int ul = p * 8 + nt * 4 + (lane & 3);
                    float2 v = *(const float2*)(mypart + rl * 64 + 2 * ul);
                    float2 w = *(const float2*)(mypart + rl * 64 + 32 + 2 * ul);
                    aif[nt][2 * hh] += v.x; aif[nt][2 * hh + 1] += v.y;
                    ago[nt][2 * hh] += w.x; ago[nt][2 * hh + 1] += w.y;
                }
        } else {
            if (tid == 0) {
                if (t) {
                    unsigned needA = 32u * (unsigned)t;
                    while (*(volatile unsigned*)&cntA[mt] < needA) {}
                }
                if (t > 8) {
                    unsigned needB = 32u * (unsigned)(t - 8);
                    while (*(volatile unsigned*)&cntB[mt] < needB) {}
                }
                __threadfence();
            }
            __syncthreads();
            if (t) run_chunks(0, 8, 0, 0);
        }

        // cell epilogue: 4 cells per thread, h -> smem tile, then coalesced publish
        __syncthreads();   // all warps done reading A buffers; reuse buffer 0 as h stage
        __nv_bfloat16* hst = (__nv_bfloat16*)sA;   // 128 rows x 16 units bf16 = 4KB
#pragma unroll
        for (int hh = 0; hh < 2; ++hh)
#pragma unroll
            for (int nt = 0; nt < 2; ++nt) {
                int rl = mh * 16 + (lane >> 2) + hh * 8;
                int ci = hh * 2 + nt;
                float gi = aif[nt][2 * hh]     + bif[nt].x;
                float gf = aif[nt][2 * hh + 1] + bif[nt].y;
                float gg = ago[nt][2 * hh]     + bgo[nt].x;
                float go = ago[nt][2 * hh + 1] + bgo[nt].y;
                if (!isL1) {
                    gi += pif[ci].x; gf += pif[ci].y;
                    gg += pgo[ci].x; go += pgo[ci].y;
                }
                creg[ci] = sigf(gf) * creg[ci] + sigf(gi) * tanhfast(gg);
                float h = sigf(go) * tanhfast(creg[ci]);
                hst[rl * 16 + (p * 8 + nt * 4 + (lane & 3))] = __float2bfloat16_rn(h);
                if (isL1 && t == Tc - 1) c1fin[(m0 + rl) * Hc + (u + nt * 4)] = creg[ci];
            }
        __syncthreads();
        if (tid < 256) {
            int rl = tid >> 1, half = tid & 1;
            *(uint4*)(hout + ((size_t)(m0 + rl) * Tc + t) * 512 + ut * 16 + half * 8) =
                *(const uint4*)(hst + rl * 16 + half * 8);
        }
        __syncthreads();
        if (tid == 0) red_release_add(&mycnt[mt], 1u);

        // L0 extra phase: compute Wih1 chunks 0..3 partial for L1 counterpart
        if (!isL1) {
            if (tid == 0) {
                unsigned needA = 32u * (unsigned)(t + 1);
                while (*(volatile unsigned*)&cntA[mt] < needA) {}
                __threadfence();
            }
            __syncthreads();
#pragma unroll
            for (int nt = 0; nt < 2; ++nt)
#pragma unroll
                for (int j = 0; j < 4; ++j) { aif[nt][j] = 0.f; ago[nt][j] = 0.f; }
            run_chunks(0, 4, 8, 1);   // W subs 8..11, A = hb0[t] chunks 0..3

            // write partial: regs -> smem pbuf (buffers 0-1) -> coalesced global
            __syncthreads();          // all warps done with A buffers 0..1 (chunk-3 top sync passed)
            float* pbuf = (float*)sA;
#pragma unroll
            for (int hh = 0; hh < 2; ++hh)
#pragma unroll
                for (int nt = 0; nt < 2; ++nt) {
                    int rl = mh * 16 + (lane >> 2) + hh * 8;
                    int ul = p * 8 + nt * 4 + (lane & 3);
                    pbuf[rl * 64 + 2 * ul]          = aif[nt][2 * hh];
                    pbuf[rl * 64 + 2 * ul + 1]      = aif[nt][2 * hh + 1];
                    pbuf[rl * 64 + 32 + 2 * ul]     = ago[nt][2 * hh];
                    pbuf[rl * 64 + 32 + 2 * ul + 1] = ago[nt][2 * hh + 1];
                }
            __syncthreads();
            float4* gp4 = (float4*)mypart;
            const float4* pb4 = (const float4*)pbuf;
            for (int i = tid; i < 2048; i += 512) gp4[i] = pb4[i];
            __syncthreads();
            if (tid == 0) red_release_add(&fP[lb], 1u);
        }
    }
}

// ---------------- fp32 GEMM tile core (decoder) ----------------
__device__ __forceinline__ void gemm_tile(
    const float* __restrict__ A, long lda,
    const float* __restrict__ W, long ldw, int K,
    ull (&acc)[4][2],
    float (&As)[32][72], float (&Bs)[32][72],
    long m0, int n0, int tid)
{
    const int lk = tid & 7, lm = tid >> 3;
    const float* ap = A + (m0 + lm) * lda + lk * 4;
    const float* wp = W + (long)(n0 + lm) * ldw + lk * 4;
    const int tm = tid >> 4, tn = tid & 15;

    for (int k0 = 0; k0 < K; k0 += 32) {
        float4 a0 = *(const float4*)(ap + k0);
        float4 a1 = *(const float4*)(ap + (long)32 * lda + k0);
        float4 w0 = *(const float4*)(wp + k0);
        float4 w1 = *(const float4*)(wp + (long)32 * ldw + k0);
        __syncthreads();
        As[lk*4+0][lm] = a0.x; As[lk*4+1][lm] = a0.y; As[lk*4+2][lm] = a0.z; As[lk*4+3][lm] = a0.w;
        As[lk*4+0][lm+32] = a1.x; As[lk*4+1][lm+32] = a1.y; As[lk*4+2][lm+32] = a1.z; As[lk*4+3][lm+32] = a1.w;
        Bs[lk*4+0][lm] = w0.x; Bs[lk*4+1][lm] = w0.y; Bs[lk*4+2][lm] = w0.z; Bs[lk*4+3][lm] = w0.w;
        Bs[lk*4+0][lm+32] = w1.x; Bs[lk*4+1][lm+32] = w1.y; Bs[lk*4+2][lm+32] = w1.z; Bs[lk*4+3][lm+32] = w1.w;
        __syncthreads();
#pragma unroll
        for (int k = 0; k < 32; ++k) {
            float4 av = *(const float4*)&As[k][tm * 4];
            float4 bv = *(const float4*)&Bs[k][tn * 4];
            ull bl = pack2(bv.x, bv.y);
            ull bh = pack2(bv.z, bv.w);
            ull aa;
            aa = pack2(av.x, av.x); fma2(acc[0][0], aa, bl); fma2(acc[0][1], aa, bh);
            aa = pack2(av.y, av.y); fma2(acc[1][0], aa, bl); fma2(acc[1][1], aa, bh);
            aa = pack2(av.z, av.z); fma2(acc[2][0], aa, bl); fma2(acc[2][1], aa, bh);
            aa = pack2(av.w, av.w); fma2(acc[3][0], aa, bl); fma2(acc[3][1], aa, bh);
        }
    }
}

template <bool HASSCAL>
__device__ __forceinline__ void cell_epilogue(
    ull (&acc)[4][2], int m0, int n0, int tid,
    const float* __restrict__ scal, const float* __restrict__ wcolp,
    const float* __restrict__ bias,
    const float* __restrict__ c_in, float* __restrict__ c_out,
    float* __restrict__ h_out)
{
    const int tm = tid >> 4, tn = tid & 15;
    const int gp0 = n0 + tn * 4;
    const int jh  = gp0 >> 2;
    float4 bi = *(const float4*)&bias[gp0];
    float4 wc = make_float4(0.f, 0.f, 0.f, 0.f);
    if (HASSCAL) wc = *(const float4*)&wcolp[gp0];

#pragma unroll
    for (int i = 0; i < 4; ++i) {
        int b = m0 + tm * 4 + i;
        float2 lo = unpack2(acc[i][0]);
        float2 hi = unpack2(acc[i][1]);
        float gi = lo.x + bi.x;
        float gf = lo.y + bi.y;
        float gg = hi.x + bi.z;
        float go = hi.y + bi.w;
        if (HASSCAL) {
            float s = scal[b];
            gi += s * wc.x; gf += s * wc.y; gg += s * wc.z; go += s * wc.w;
        }
        float cprev = c_in[b * Hc + jh];
        float cnew  = sigf(gf) * cprev + sigf(gi) * tanhfast(gg);
        float hnew  = sigf(go) * tanhfast(cnew);
        c_out[b * Hc + jh] = cnew;
        h_out[(long)b * Hc + jh] = hnew;
    }
}

// ---------------- softmax + context (bf16 encoder history) ----------------
__device__ __forceinline__ void softmax_ctx_one(
    int b, const float* __restrict__ energy, const __nv_bfloat16* __restrict__ hb1,
    float* __restrict__ ctx, float (&sm)[Tc], float (&red)[256], int tid)
{
    float e0 = energy[b * Tc + tid];
    float e1 = energy[b * Tc + tid + 256];
    red[tid] = fmaxf(e0, e1);
    __syncthreads();
    for (int s = 128; s; s >>= 1) {
        if (tid < s) red[tid] = fmaxf(red[tid], red[tid + s]);
        __syncthreads();
    }
    float m = red[0];
    __syncthreads();
    float p0 = __expf(e0 - m), p1 = __expf(e1 - m);
    sm[tid] = p0; sm[tid + 256] = p1;
    red[tid] = p0 + p1;
    __syncthreads();
    for (int s = 128; s; s >>= 1) {
        if (tid < s) red[tid] += red[tid + s];
        __syncthreads();
    }
    float inv = __fdividef(1.0f, red[0]);
    __syncthreads();
    sm[tid] *= inv; sm[tid + 256] *= inv;
    __syncthreads();

    const __nv_bfloat16* base = hb1 + (size_t)b * Tc * 512 + tid * 2;
    float2 acc = make_float2(0.f, 0.f);
#pragma unroll 4
    for (int t = 0; t < Tc; ++t) {
        __nv_bfloat162 e = *(const __nv_bfloat162*)(base + (size_t)t * 512);
        float2 ef = __bfloat1622float2(e);
        float a = sm[t];
        acc.x += a * ef.x; acc.y += a * ef.y;
    }
    *(float2*)&ctx[b * Hc + tid * 2] = acc;
    __syncthreads();
}

// ---------------- persistent decoder ----------------
__global__ void __launch_bounds__(256) decoder_persistent(
    const __nv_bfloat16* __restrict__ hb1, const __nv_bfloat16* __restrict__ encprj,
    const float* __restrict__ c1,
    const float* __restrict__ attnW, const float* __restrict__ attnv,
    const float* __restrict__ dwrest, const float* __restrict__ dwcol,
    const float* __restrict__ dWhh0p, const float* __restrict__ dWih1p,
    const float* __restrict__ dWhh1p,
    const float* __restrict__ bD0, const float* __restrict__ bD1,
    const float* __restrict__ outW, const float* __restrict__ outb,
    float* __restrict__ hd0, float* __restrict__ hd1,
    float* __restrict__ cd0, float* __restrict__ cd1,
    float* __restrict__ h0tmp, float* __restrict__ cdump,
    float* __restrict__ ctx, float* __restrict__ decprj,
    float* __restrict__ energy, float* __restrict__ dinp,
    float* __restrict__ dout)
{
    __shared__ float As[32][72];
    __shared__ float Bs[32][72];
    __shared__ float sm[Tc];
    __shared__ float red[256];
    __shared__ float sdp[2][512];
    __shared__ float sv[512];
    const int tid = threadIdx.x, bid = blockIdx.x;
    const int mt = bid & 3, nt = bid >> 2;
    const int warp = tid >> 5, lane = tid & 31;

    for (int i = bid * 256 + tid; i < Bc * Hc; i += NBLK * 256) {
        int b = i >> 9, h = i & (Hc - 1);
        hd0[i] = __bfloat162float(hb1[((size_t)b * Tc + (Tc - 1)) * 512 + h]);
        cd0[i] = c1[i];
    }
    for (int i = tid; i < 512; i += 256) sv[i] = attnv[i];
    grid_sync();

    float* hcur = hd0; float* ccur = cd0;
    float* hnext = hd1; float* cnext = cd1;

    for (int s = 0; s < HOR; ++s) {
        if (bid < 32) {
            ull acc[4][2];
#pragma unroll
            for (int i = 0; i < 4; ++i) { acc[i][0] = 0ull; acc[i][1] = 0ull; }
            int m0 = (bid & 3) * 64, n0 = (bid >> 2) * 64;
            gemm_tile(hcur, (long)Hc, attnW, (long)Hc, Hc, acc, As, Bs, (long)m0, n0, tid);
            const int tm = tid >> 4, tn = tid & 15;
#pragma unroll
            for (int i = 0; i < 4; ++i) {
                float2 lo = unpack2(acc[i][0]);
                float2 hi = unpack2(acc[i][1]);
                *(float4*)(decprj + (long)(m0 + tm * 4 + i) * Hc + n0 + tn * 4) =
                    make_float4(lo.x, lo.y, hi.x, hi.y);
            }
        }
        grid_sync();

        // energy: 1024 rows per block (2 batches), dproj + v cached in smem
        {
            for (int i = tid; i < 512; i += 256) {
                sdp[0][i] = decprj[(bid * 2) * Hc + i];
                sdp[1][i] = decprj[(bid * 2 + 1) * Hc + i];
            }
            __syncthreads();
            const float2* svf2 = (const float2*)sv;
            int row0 = bid * 1024 + warp * 128;
            for (int r = 0; r < 128; ++r) {
                int row = row0 + r;
                int local = (row >> 9) & 1;
                const __nv_bfloat162* ep2 = (const __nv_bfloat162*)(encprj + (size_t)row * Hc);
                const float2* dp2 = (const float2*)sdp[local];
                float part = 0.f;
#pragma unroll
                for (int i = 0; i < 8; ++i) {
                    int pidx = lane + 32 * i;
                    float2 ef = __bfloat1622float2(ep2[pidx]);
                    float2 df = dp2[pidx];
                    float2 vf = svf2[pidx];
                    part += tanh_hw(ef.x + df.x) * vf.x + tanh_hw(ef.y + df.y) * vf.y;
                }
#pragma unroll
                for (int o = 16; o; o >>= 1) part += __shfl_xor_sync(~0u, part, o);
                if (lane == 0) energy[row] = part;
            }
        }
        grid_sync();

        softmax_ctx_one(bid * 2 + 0, energy, hb1, ctx, sm, red, tid);
        softmax_ctx_one(bid * 2 + 1, energy, hb1, ctx, sm, red, tid);
        grid_sync();

        {
            ull acc[4][2];
#pragma unroll
            for (int i = 0; i < 4; ++i) { acc[i][0] = 0ull; acc[i][1] = 0ull; }
            int m0 = mt * 64, n0 = nt * 64;
            gemm_tile(ctx,  (long)Hc, dwrest, (long)Hc, Hc, acc, As, Bs, (long)m0, n0, tid);
            gemm_tile(hcur, (long)Hc, dWhh0p, (long)Hc, Hc, acc, As, Bs, (long)m0, n0, tid);
            cell_epilogue<true>(acc, m0, n0, tid, dinp, dwcol, bD0, ccur, cdump, h0tmp);
        }
        grid_sync();

        {
            ull acc[4][2];
#pragma unroll
            for (int i = 0; i < 4; ++i) { acc[i][0] = 0ull; acc[i][1] = 0ull; }
            int m0 = mt * 64, n0 = nt * 64;
            gemm_tile(h0tmp, (long)Hc, dWih1p, (long)Hc, Hc, acc, As, Bs, (long)m0, n0, tid);
            gemm_tile(hcur,  (long)Hc, dWhh1p, (long)Hc, Hc, acc, As, Bs, (long)m0, n0, tid);
            cell_epilogue<false>(acc, m0, n0, tid, nullptr, nullptr, bD1, ccur, cnext, hnext);
        }
        grid_sync();

        {
            int w = bid * 8 + warp;
            if (w < Bc * NQc) {
                int b = w / 3, q = w - b * 3;
                const float* hr = hnext + b * Hc;
                const float* wr = outW + q * Hc;
                float part = 0.f;
#pragma unroll
                for (int i = 0; i < 16; ++i) part += hr[lane + 32 * i] * wr[lane + 32 * i];
#pragma unroll
                for (int o = 16; o; o >>= 1) part += __shfl_xor_sync(~0u, part, o);
                if (lane == 0) {
                    float val = part + outb[q];
                    dout[(long)b * (HOR * NQc) + s * NQc + q] = val;
                    if (q == 1) dinp[b] = val;
                }
            }
        }
        grid_sync();

        float* th = hcur; hcur = hnext; hnext = th;
        float* tc = ccur; ccur = cnext; cnext = tc;
    }
}

// ---------------- host ----------------
template <typename T>
static T* sym_addr(const void* symbol) {
    void* p = nullptr;
    cudaGetSymbolAddress(&p, symbol);
    return (T*)p;
}

extern "C" void kernel_launch(void* const* d_in, const int* in_sizes, int n_in,
                              void* d_out, int out_size)
{
    const float* x      = (const float*)d_in[0];
    const float* eWih0  = (const float*)d_in[1];
    const float* eWhh0  = (const float*)d_in[2];
    const float* ebih0  = (const float*)d_in[3];
    const float* ebhh0  = (const float*)d_in[4];
    const float* eWih1  = (const float*)d_in[5];
    const float* eWhh1  = (const float*)d_in[6];
    const float* ebih1  = (const float*)d_in[7];
    const float* ebhh1  = (const float*)d_in[8];
    const float* dWih0  = (const float*)d_in[9];
    const float* dWhh0  = (const float*)d_in[10];
    const float* dbih0  = (const float*)d_in[11];
    const float* dbhh0  = (const float*)d_in[12];
    const float* dWih1  = (const float*)d_in[13];
    const float* dWhh1  = (const float*)d_in[14];
    const float* dbih1  = (const float*)d_in[15];
    const float* dbhh1  = (const float*)d_in[16];
    const float* attnW  = (const float*)d_in[17];
    const float* attnv  = (const float*)d_in[18];
    const float* outW   = (const float*)d_in[19];
    const float* outb   = (const float*)d_in[20];
    float* dout = (float*)d_out;

    float* pre    = sym_addr<float>(g_pre);
    __nv_bfloat16* xb    = sym_addr<__nv_bfloat16>(g_xb);
    __nv_bfloat16* hb0   = sym_addr<__nv_bfloat16>(g_hb0);
    __nv_bfloat16* hb1   = sym_addr<__nv_bfloat16>(g_hb1);
    __nv_bfloat16* Wih0b = sym_addr<__nv_bfloat16>(g_Wih0b);
    __nv_bfloat16* Whh0b = sym_addr<__nv_bfloat16>(g_Whh0b);
    __nv_bfloat16* Wih1b = sym_addr<__nv_bfloat16>(g_Wih1b);
    __nv_bfloat16* Whh1b = sym_addr<__nv_bfloat16>(g_Whh1b);
    __nv_bfloat16* attnWb = sym_addr<__nv_bfloat16>(g_attnWb);
    __nv_bfloat16* encprj = sym_addr<__nv_bfloat16>(g_encproj);
    float* partb  = sym_addr<float>(g_part);
    float* bE0    = sym_addr<float>(g_bE0p2);
    float* bE1    = sym_addr<float>(g_bE1p2);
    float* dwrest = sym_addr<float>(g_dwrestp);
    float* dWhh0p = sym_addr<float>(g_dWhh0p);
    float* dWih1p = sym_addr<float>(g_dWih1p);
    float* dWhh1p = sym_addr<float>(g_dWhh1p);
    float* dwcol  = sym_addr<float>(g_dwcol0p);
    float* bD0    = sym_addr<float>(g_bD0p);
    float* bD1    = sym_addr<float>(g_bD1p);
    float* c1     = sym_addr<float>(g_c1);
    float* hd0    = sym_addr<float>(g_hd0);
    float* hd1    = sym_addr<float>(g_hd1);
    float* cd0    = sym_addr<float>(g_cd0);
    float* cd1    = sym_addr<float>(g_cd1);
    float* cdump  = sym_addr<float>(g_cdump);
    float* h0tmp  = sym_addr<float>(g_h0tmp);
    float* ctx    = sym_addr<float>(g_ctx);
    float* decprj = sym_addr<float>(g_decproj);
    float* energy = sym_addr<float>(g_energy);
    float* dinp   = sym_addr<float>(g_dinp);
    unsigned* cntA = sym_addr<unsigned>(g_cntA);
    unsigned* cntB = sym_addr<unsigned>(g_cntB);
    unsigned* fP   = sym_addr<unsigned>(g_fP);

    constexpr int ENC_SMEM = 12 * 8192 + 4 * 16384;   // 160KB
    cudaFuncSetAttribute(enc_overlap, cudaFuncAttributeMaxDynamicSharedMemorySize, ENC_SMEM);

    // 0) prep
    prep_kernel<<<(Bc * Tc * Ic + 255) / 256, 256>>>(
        x, eWih0, eWhh0, ebih0, ebhh0, eWih1, eWhh1, ebih1, ebhh1,
        dWih0, dWhh0, dbih0, dbhh0, dWih1, dWhh1, dbih1, dbhh1, attnW);

    // 1) P0 = xb @ Wih0b^T  (K=64, pair-permuted output into pre)
    gemm_bf16pair<<<dim3(Bc * Tc / 64, 16), 256>>>(xb, Ic, Wih0b, Ic, Ic, pre, Gc);

    // 2) overlapped dual-layer encoder with partial offload (1 launch)
    enc_overlap<<<NBLK, 512, ENC_SMEM>>>(
        hb0, hb1, Whh0b, Wih1b, Whh1b, pre, bE0, bE1, cntA, cntB, fP, partb, c1);

    // 3) enc_proj = hb1 @ attnWb^T (bf16 in, bf16 out)
    gemm_bf16pb<<<dim3(Bc * Tc / 64, 4), 256>>>(hb1, Hc, attnWb, Hc, Hc, encprj, Hc);

    // 4) decoder, all 30 steps
    decoder_persistent<<<NBLK, 256>>>(
        hb1, encprj, c1, attnW, attnv,
        dwrest, dwcol, dWhh0p, dWih1p, dWhh1p, bD0, bD1, outW, outb,
        hd0, hd1, cd0, cd1, h0tmp, cdump, ctx, decprj, energy, dinp, dout);
}

// round 17
// speedup vs baseline: 1.1961x; 1.1961x over previous
#include <cuda_runtime.h>
#include <cuda_bf16.h>
#include <cstddef>
#include <cstdint>

typedef unsigned long long ull;

// ---------------- problem constants ----------------
constexpr int Bc  = 256;
constexpr int Tc  = 512;
constexpr int Ic  = 64;
constexpr int Hc  = 512;
constexpr int Gc  = 4 * Hc;      // 2048
constexpr int HOR = 30;
constexpr int NQc = 3;
constexpr int NBLK = 128;

// ---------------- device scratch ----------------
__device__ float g_pre[(size_t)Bc * Tc * Gc];                // (B*T,2048) pair-permuted L0 pre-projections
__device__ __nv_bfloat16 g_xb[(size_t)Bc * Tc * Ic];         // x in bf16
__device__ __nv_bfloat16 g_hb0[(size_t)Bc * Tc * Hc];        // layer-0 h history (B,T,512)
__device__ __nv_bfloat16 g_hb1[(size_t)Bc * Tc * Hc];        // layer-1 h history
__device__ __nv_bfloat16 g_encproj[(size_t)Bc * Tc * Hc];    // bf16 enc_out @ attn_W^T

// encoder weights bf16, pair-permuted rows (n<1024: (i,f) of unit n>>1; n>=1024: (g,o))
__device__ __nv_bfloat16 g_Wih0b[Gc * Ic];
__device__ __nv_bfloat16 g_Whh0b[Gc * Hc];
__device__ __nv_bfloat16 g_Wih1b[Gc * Hc];
__device__ __nv_bfloat16 g_Whh1b[Gc * Hc];
__device__ __nv_bfloat16 g_attnWb[Hc * Hc];                  // plain layout bf16
__device__ float g_bE0p2[Gc];
__device__ float g_bE1p2[Gc];

// decoder weights: bf16, pair-permuted rows, K-concatenated (K=1024)
__device__ __nv_bfloat16 g_dW1b[(size_t)Gc * 1024];          // [ctx-part | h-part] for cell1
__device__ __nv_bfloat16 g_dW2b[(size_t)Gc * 1024];          // [h0-part | h-part] for cell2
__device__ float g_bD0p2[Gc];
__device__ float g_bD1p2[Gc];
__device__ float g_dwcol0p2[Gc];

// decoder activation buffers (bf16, double-buffered on h halves)
__device__ __nv_bfloat16 g_dab1[2][(size_t)Bc * 1024];       // cols 0-511 ctx, 512-1023 h
__device__ __nv_bfloat16 g_dab2[2][(size_t)Bc * 1024];       // cols 0-511 h0, 512-1023 h
__device__ float g_hdf[Bc * Hc];                              // fp32 h for out projection
__device__ float g_cd0[Bc * Hc];
__device__ float g_cd1[Bc * Hc];
__device__ float g_c1[Bc * Hc];
__device__ float g_decproj[Bc * Hc];
__device__ float g_energy[Bc * Tc];
__device__ float g_dinp[Bc];

// encoder pipeline counters (zeroed by prep each run): [mt] per layer
__device__ unsigned g_cntA[2];
__device__ unsigned g_cntB[2];

// decoder global barrier (self-resetting)
__device__ unsigned g_arrive = 0;
__device__ unsigned g_release = 0;

__device__ __forceinline__ void grid_sync() {
    __syncthreads();
    if (threadIdx.x == 0) {
        __threadfence();
        unsigned prev = *((volatile unsigned*)&g_release);
        unsigned a = atomicAdd(&g_arrive, 1u);
        if (a == gridDim.x - 1u) {
            atomicExch(&g_arrive, 0u);
            __threadfence();
            atomicExch(&g_release, prev + 1u);
        } else {
            while (*((volatile unsigned*)&g_release) == prev) __nanosleep(64);
        }
        __threadfence();
    }
    __syncthreads();
}

// ---------------- math helpers ----------------
__device__ __forceinline__ float sigf(float x) {
    return __fdividef(1.0f, 1.0f + __expf(-x));
}
__device__ __forceinline__ float tanhfast(float x) {
    return 1.0f - __fdividef(2.0f, __expf(2.0f * x) + 1.0f);
}
__device__ __forceinline__ float tanh_hw(float x) {
    float y; asm("tanh.approx.f32 %0, %1;" : "=f"(y) : "f"(x)); return y;
}
__device__ __forceinline__ void red_release_add(unsigned* p, unsigned v) {
    asm volatile("red.release.gpu.global.add.u32 [%0], %1;" :: "l"(p), "r"(v) : "memory");
}

// ---------------- async copy helpers ----------------
__device__ __forceinline__ void cp_async16(uint32_t dst, const void* src) {
    asm volatile("cp.async.cg.shared.global [%0], [%1], 16;" :: "r"(dst), "l"(src));
}
__device__ __forceinline__ void cp_commit() {
    asm volatile("cp.async.commit_group;");
}
template<int N>
__device__ __forceinline__ void cp_wait() {
    asm volatile("cp.async.wait_group %0;" :: "n"(N));
}

// ---------------- tensor-core helpers ----------------
__device__ __forceinline__ void ldsm_x4(uint32_t (&r)[4], uint32_t addr) {
    asm volatile("ldmatrix.sync.aligned.m8n8.x4.shared.b16 {%0,%1,%2,%3}, [%4];"
        : "=r"(r[0]), "=r"(r[1]), "=r"(r[2]), "=r"(r[3]) : "r"(addr));
}
__device__ __forceinline__ void ldsm_x2(uint32_t (&r)[2], uint32_t addr) {
    asm volatile("ldmatrix.sync.aligned.m8n8.x2.shared.b16 {%0,%1}, [%2];"
        : "=r"(r[0]), "=r"(r[1]) : "r"(addr));
}
__device__ __forceinline__ void mma16816(float (&d)[4], const uint32_t (&a)[4], const uint32_t (&b)[2]) {
    asm volatile("mma.sync.aligned.m16n8k16.row.col.f32.bf16.bf16.f32 "
        "{%0,%1,%2,%3}, {%4,%5,%6,%7}, {%8,%9}, {%0,%1,%2,%3};"
        : "+f"(d[0]), "+f"(d[1]), "+f"(d[2]), "+f"(d[3])
        : "r"(a[0]), "r"(a[1]), "r"(a[2]), "r"(a[3]), "r"(b[0]), "r"(b[1]));
}

// ---------------- prep ----------------
__global__ void prep_kernel(const float* __restrict__ x,
    const float* __restrict__ eWih0, const float* __restrict__ eWhh0,
    const float* __restrict__ ebih0, const float* __restrict__ ebhh0,
    const float* __restrict__ eWih1, const float* __restrict__ eWhh1,
    const float* __restrict__ ebih1, const float* __restrict__ ebhh1,
    const float* __restrict__ dWih0, const float* __restrict__ dWhh0,
    const float* __restrict__ dbih0, const float* __restrict__ dbhh0,
    const float* __restrict__ dWih1, const float* __restrict__ dWhh1,
    const float* __restrict__ dbih1, const float* __restrict__ dbhh1,
    const float* __restrict__ attnW)
{
    int idx = blockIdx.x * 256 + threadIdx.x;   // grid covers B*T*I = 8,388,608

    if (idx < Bc * Tc * Ic) g_xb[idx] = __float2bfloat16_rn(x[idx]);

    if (idx < Gc * Hc) {
        int n = idx / Hc;
        int k = idx - n * Hc;

        // pair permutation: n<1024: (i,f) of unit n>>1; n>=1024: (g,o)
        int q  = (n < 1024) ? (n & 1) : 2 + (n & 1);
        int jh = ((n < 1024) ? n : n - 1024) >> 1;
        int g2 = q * Hc + jh;
        size_t s2 = (size_t)g2 * Hc + k;

        // encoder bf16
        g_Whh0b[idx] = __float2bfloat16_rn(eWhh0[s2]);
        g_Wih1b[idx] = __float2bfloat16_rn(eWih1[s2]);
        g_Whh1b[idx] = __float2bfloat16_rn(eWhh1[s2]);
        if (k < Ic) g_Wih0b[(size_t)n * Ic + k] = __float2bfloat16_rn(eWih0[(size_t)g2 * Ic + k]);

        // decoder bf16, K-concatenated
        g_dW1b[(size_t)n * 1024 + k]       = __float2bfloat16_rn(dWih0[(size_t)g2 * (Hc + 1) + 1 + k]);
        g_dW1b[(size_t)n * 1024 + 512 + k] = __float2bfloat16_rn(dWhh0[s2]);
        g_dW2b[(size_t)n * 1024 + k]       = __float2bfloat16_rn(dWih1[s2]);
        g_dW2b[(size_t)n * 1024 + 512 + k] = __float2bfloat16_rn(dWhh1[s2]);

        if (k == 0) {
            g_bE0p2[n] = ebih0[g2] + ebhh0[g2];
            g_bE1p2[n] = ebih1[g2] + ebhh1[g2];
            g_bD0p2[n] = dbih0[g2] + dbhh0[g2];
            g_bD1p2[n] = dbih1[g2] + dbhh1[g2];
            g_dwcol0p2[n] = dWih0[(size_t)g2 * (Hc + 1)];
        }
    }

    if (idx < Hc * Hc) g_attnWb[idx] = __float2bfloat16_rn(attnW[idx]);
    if (idx < 2) { g_cntA[idx] = 0u; g_cntB[idx] = 0u; }
    if (idx < Bc) g_dinp[idx] = x[(size_t)idx * Tc * Ic + (size_t)(Tc - 1) * Ic];
}

// ---------------- HMMA streaming core (256 threads, M=MF*16, N=64+64) ----------------
template<int MF>
__device__ __forceinline__ void hmma_core(
    const __nv_bfloat16* __restrict__ A, size_t lda,
    const __nv_bfloat16* __restrict__ Wif, const __nv_bfloat16* __restrict__ Wgo,
    size_t ldw, int kchunks,
    float (&aif)[MF][4], float (&ago)[MF][4],
    char* sA, char* sW, int tid, int wid, int lane)
{
    uint32_t sAb = (uint32_t)__cvta_generic_to_shared(sA);
    uint32_t sWb = (uint32_t)__cvta_generic_to_shared(sW);
    const int lr = lane & 15, hb = lane >> 4;
    const int nb = wid * 8 + (lane & 7), bsel = (lane >> 3) & 1;

    for (int kc = 0; kc < kchunks; ++kc) {
        __syncthreads();
#pragma unroll
        for (int j = 0; j < MF / 2; ++j) {
            int i = tid + j * 256;
            int r = i >> 3, c = i & 7;
            *(uint4*)(sA + ((r * 8 + (c ^ (r & 7))) << 4)) =
                *(const uint4*)(A + (size_t)r * lda + kc * 64 + c * 8);
        }
#pragma unroll
        for (int j = 0; j < 2; ++j) {
            int i = tid + j * 256;
            int r = i >> 3, c = i & 7;
            *(uint4*)(sW + ((r * 8 + (c ^ (r & 7))) << 4)) =
                *(const uint4*)(Wif + (size_t)r * ldw + kc * 64 + c * 8);
            *(uint4*)(sW + 8192 + ((r * 8 + (c ^ (r & 7))) << 4)) =
                *(const uint4*)(Wgo + (size_t)r * ldw + kc * 64 + c * 8);
        }
        __syncthreads();
#pragma unroll
        for (int s = 0; s < 4; ++s) {
            uint32_t b_if[2], b_go[2];
            int cb = 2 * s + bsel;
            uint32_t boff = (uint32_t)((nb * 8 + (cb ^ (nb & 7))) << 4);
            ldsm_x2(b_if, sWb + boff);
            ldsm_x2(b_go, sWb + 8192u + boff);
            int ca = 2 * s + hb;
#pragma unroll
            for (int mf = 0; mf < MF; ++mf) {
                uint32_t a[4];
                int row = mf * 16 + lr;
                ldsm_x4(a, sAb + (uint32_t)((row * 8 + (ca ^ (lr & 7))) << 4));
                mma16816(aif[mf], a, b_if);
                mma16816(ago[mf], a, b_go);
            }
        }
    }
}

// one-shot bf16 GEMM into pair-permuted gate layout (for P0), fp32 out
__global__ void __launch_bounds__(256) gemm_bf16pair(
    const __nv_bfloat16* __restrict__ A, size_t lda,
    const __nv_bfloat16* __restrict__ Ws, size_t ldw, int K,
    float* __restrict__ C, size_t ldc)
{
    constexpr int MF = 4;
    __shared__ __align__(16) char sA[MF * 16 * 128];
    __shared__ __align__(16) char sW[128 * 128];
    const int tid = threadIdx.x, wid = tid >> 5, lane = tid & 31;
    const size_t m0 = (size_t)blockIdx.x * (MF * 16);
    const int ny = blockIdx.y;

    float aif[MF][4], ago[MF][4];
#pragma unroll
    for (int i = 0; i < MF; ++i)
#pragma unroll
        for (int j = 0; j < 4; ++j) { aif[i][j] = 0.f; ago[i][j] = 0.f; }

    hmma_core<MF>(A + m0 * lda, lda,
                  Ws + (size_t)(ny * 64) * ldw,
                  Ws + (size_t)(1024 + ny * 64) * ldw,
                  ldw, K / 64, aif, ago, sA, sW, tid, wid, lane);

    const int local = 2 * (wid * 4 + (lane & 3));
    size_t cif = (size_t)ny * 64 + local;
    size_t cgo = 1024 + (size_t)ny * 64 + local;
    const int r0 = lane >> 2;
#pragma unroll
    for (int mf = 0; mf < MF; ++mf) {
        size_t row = m0 + mf * 16 + r0;
        *(float2*)(C + row * ldc + cif)       = make_float2(aif[mf][0], aif[mf][1]);
        *(float2*)(C + (row + 8) * ldc + cif) = make_float2(aif[mf][2], aif[mf][3]);
        *(float2*)(C + row * ldc + cgo)       = make_float2(ago[mf][0], ago[mf][1]);
        *(float2*)(C + (row + 8) * ldc + cgo) = make_float2(ago[mf][2], ago[mf][3]);
    }
}

// one-shot bf16 GEMM, plain layout, bf16 output (for encproj)
__global__ void __launch_bounds__(256) gemm_bf16pb(
    const __nv_bfloat16* __restrict__ A, size_t lda,
    const __nv_bfloat16* __restrict__ Ws, size_t ldw, int K,
    __nv_bfloat16* __restrict__ C, size_t ldc)
{
    constexpr int MF = 4;
    __shared__ __align__(16) char sA[MF * 16 * 128];
    __shared__ __align__(16) char sW[128 * 128];
    const int tid = threadIdx.x, wid = tid >> 5, lane = tid & 31;
    const size_t m0 = (size_t)blockIdx.x * (MF * 16);
    const int ny = blockIdx.y;

    float acc0[MF][4], acc1[MF][4];
#pragma unroll
    for (int i = 0; i < MF; ++i)
#pragma unroll
        for (int j = 0; j < 4; ++j) { acc0[i][j] = 0.f; acc1[i][j] = 0.f; }

    hmma_core<MF>(A + m0 * lda, lda,
                  Ws + (size_t)(ny * 128) * ldw,
                  Ws + (size_t)(ny * 128 + 64) * ldw,
                  ldw, K / 64, acc0, acc1, sA, sW, tid, wid, lane);

    const int local = 2 * (wid * 4 + (lane & 3));
    size_t c0 = (size_t)ny * 128 + local;
    size_t c1 = (size_t)ny * 128 + 64 + local;
    const int r0 = lane >> 2;
#pragma unroll
    for (int mf = 0; mf < MF; ++mf) {
        size_t row = m0 + mf * 16 + r0;
        *(__nv_bfloat162*)(C + row * ldc + c0) =
            __float22bfloat162_rn(make_float2(acc0[mf][0], acc0[mf][1]));
        *(__nv_bfloat162*)(C + (row + 8) * ldc + c0) =
            __float22bfloat162_rn(make_float2(acc0[mf][2], acc0[mf][3]));
        *(__nv_bfloat162*)(C + row * ldc + c1) =
            __float22bfloat162_rn(make_float2(acc1[mf][0], acc1[mf][1]));
        *(__nv_bfloat162*)(C + (row + 8) * ldc + c1) =
            __float22bfloat162_rn(make_float2(acc1[mf][2], acc1[mf][3]));
    }
}

// ---------------- overlapped dual-layer persistent encoder (R14 best) ----------------
__global__ void __launch_bounds__(512, 1) enc_overlap(
    __nv_bfloat16* __restrict__ hb0, __nv_bfloat16* __restrict__ hb1,
    const __nv_bfloat16* __restrict__ Whh0b,
    const __nv_bfloat16* __restrict__ Wih1b, const __nv_bfloat16* __restrict__ Whh1b,
    const float* __restrict__ pre,
    const float* __restrict__ bE0, const float* __restrict__ bE1,
    unsigned* __restrict__ cntA, unsigned* __restrict__ cntB,
    float* __restrict__ c1fin)
{
    extern __shared__ __align__(16) char smem[];   // W subs then 4 x 16KB A buffers
    const int tid = threadIdx.x, wid = tid >> 5, lane = tid & 31;
    const bool isL1 = (blockIdx.x >= 64);
    const int lb = blockIdx.x & 63;
    const int mt = lb >> 5, ut = lb & 31;
    const int m0 = mt * 128;
    const int NS = isL1 ? 16 : 8;
    const int p = wid & 1, mh = wid >> 1;

    for (int i = tid; i < NS * 512; i += 512) {
        int sub = i >> 9;
        int rem = i & 511;
        int r = rem >> 3, c8 = rem & 7;
        int grow = (r < 32) ? (ut * 32 + r) : (1024 + ut * 32 + (r - 32));
        const __nv_bfloat16* src;
        if (!isL1) src = Whh0b + (size_t)grow * 512 + sub * 64 + c8 * 8;
        else       src = (sub < 8) ? (Wih1b + (size_t)grow * 512 + sub * 64 + c8 * 8)
                                   : (Whh1b + (size_t)grow * 512 + (sub - 8) * 64 + c8 * 8);
        *(uint4*)(smem + sub * 8192 + ((r * 8 + (c8 ^ (r & 7))) << 4)) = *(const uint4*)src;
    }

    const float* bias = isL1 ? bE1 : bE0;
    const int u = ut * 16 + p * 8 + (lane & 3);
    float2 bif[2], bgo[2];
#pragma unroll
    for (int nt = 0; nt < 2; ++nt) {
        bif[nt] = *(const float2*)(bias + 2 * (u + nt * 4));
        bgo[nt] = *(const float2*)(bias + 1024 + 2 * (u + nt * 4));
    }
    float creg[4] = {0.f, 0.f, 0.f, 0.f};
    __syncthreads();

    const uint32_t sWb32 = (uint32_t)__cvta_generic_to_shared(smem);
    const uint32_t sAb32 = sWb32 + (uint32_t)(NS * 8192);
    char* sA = smem + NS * 8192;
    const int r0 = tid >> 2, c20 = (tid & 3) * 2;
    __nv_bfloat16* hout = isL1 ? hb1 : hb0;
    unsigned* mycnt = isL1 ? cntB : cntA;

    for (int t = 0; t < Tc; ++t) {
        float2 pif[4], pgo[4];
        if (!isL1) {
#pragma unroll
            for (int hh = 0; hh < 2; ++hh)
#pragma unroll
                for (int nt = 0; nt < 2; ++nt) {
                    int row = m0 + mh * 16 + (lane >> 2) + hh * 8;
                    const float* Pr = pre + ((size_t)row * Tc + t) * 2048;
                    pif[hh * 2 + nt] = *(const float2*)(Pr + 2 * (u + nt * 4));
                    pgo[hh * 2 + nt] = *(const float2*)(Pr + 1024 + 2 * (u + nt * 4));
                }
        }

        float aif[2][4], ago[2][4];
#pragma unroll
        for (int nt = 0; nt < 2; ++nt)
#pragma unroll
            for (int j = 0; j < 4; ++j) { aif[nt][j] = 0.f; ago[nt][j] = 0.f; }

        auto stage = [&](int kc) {
            const __nv_bfloat16* base;
            if (!isL1) base = hb0 + ((size_t)(m0 + r0) * Tc + (t - 1)) * 512 + kc * 64;
            else base = (kc < 8) ? (hb0 + ((size_t)(m0 + r0) * Tc + t) * 512 + kc * 64)
                                 : (hb1 + ((size_t)(m0 + r0) * Tc + (t - 1)) * 512 + (kc - 8) * 64);
            uint32_t bufb = sAb32 + (uint32_t)((kc & 3) * 16384);
            cp_async16(bufb + (uint32_t)((r0 * 8 + (c20 ^ (r0 & 7))) << 4), base + c20 * 8);
            cp_async16(bufb + (uint32_t)((r0 * 8 + ((c20 + 1) ^ (r0 & 7))) << 4), base + (c20 + 1) * 8);
        };

        auto run_chunks = [&](int kc0, int kcn) {
            stage(kc0); cp_commit();
            if (kc0 + 1 < kcn) { stage(kc0 + 1); }
            cp_commit();
            for (int kc = kc0; kc < kcn; ++kc) {
                if (kc + 2 < kcn) stage(kc + 2);
                cp_commit();
                cp_wait<2>();
                __syncthreads();

                uint32_t wsub = sWb32 + (uint32_t)(kc * 8192);
                uint32_t asub = sAb32 + (uint32_t)((kc & 3) * 16384);
#pragma unroll
                for (int ks = 0; ks < 4; ++ks) {
                    int cb = 2 * ks + ((lane >> 3) & 1);
                    uint32_t b_if[2][2], b_go[2][2];
#pragma unroll
                    for (int nt = 0; nt < 2; ++nt) {
                        int rb = p * 16 + nt * 8 + (lane & 7);
                        ldsm_x2(b_if[nt], wsub + (uint32_t)((rb * 8 + (cb ^ (rb & 7))) << 4));
                        int rg = rb + 32;
                        ldsm_x2(b_go[nt], wsub + (uint32_t)((rg * 8 + (cb ^ (rg & 7))) << 4));
                    }
                    int ra = mh * 16 + (lane & 15);
                    int ca = 2 * ks + (lane >> 4);
                    uint32_t a[4];
                    ldsm_x4(a, asub + (uint32_t)((ra * 8 + (ca ^ (ra & 7))) << 4));
                    mma16816(aif[0], a, b_if[0]);
                    mma16816(aif[1], a, b_if[1]);
                    mma16816(ago[0], a, b_go[0]);
                    mma16816(ago[1], a, b_go[1]);
                }
            }
        };

        if (isL1) {
            if (tid == 0) {
                unsigned needA = 32u * (unsigned)(t + 1);
                while (*(volatile unsigned*)&cntA[mt] < needA) {}
                __threadfence();
            }
            __syncthreads();
            run_chunks(0, 8);

            if (t) {
                if (tid == 0) {
                    unsigned needB = 32u * (unsigned)t;
                    while (*(volatile unsigned*)&cntB[mt] < needB) {}
                    __threadfence();
                }
                __syncthreads();
                run_chunks(8, 16);
            }
        } else {
            if (tid == 0) {
                if (t) {
                    unsigned needA = 32u * (unsigned)t;
                    while (*(volatile unsigned*)&cntA[mt] < needA) {}
                }
                if (t > 8) {
                    unsigned needB = 32u * (unsigned)(t - 8);
                    while (*(volatile unsigned*)&cntB[mt] < needB) {}
                }
                __threadfence();
            }
            __syncthreads();
            if (t) run_chunks(0, 8);
        }

        __syncthreads();
        __nv_bfloat16* hst = (__nv_bfloat16*)sA;
#pragma unroll
        for (int hh = 0; hh < 2; ++hh)
#pragma unroll
            for (int nt = 0; nt < 2; ++nt) {
                int rl = mh * 16 + (lane >> 2) + hh * 8;
                int ci = hh * 2 + nt;
                float gi = aif[nt][2 * hh]     + bif[nt].x;
                float gf = aif[nt][2 * hh + 1] + bif[nt].y;
                float gg = ago[nt][2 * hh]     + bgo[nt].x;
                float go = ago[nt][2 * hh + 1] + bgo[nt].y;
                if (!isL1) {
                    gi += pif[ci].x; gf += pif[ci].y;
                    gg += pgo[ci].x; go += pgo[ci].y;
                }
                creg[ci] = sigf(gf) * creg[ci] + sigf(gi) * tanhfast(gg);
                float h = sigf(go) * tanhfast(creg[ci]);
                hst[rl * 16 + (p * 8 + nt * 4 + (lane & 3))] = __float2bfloat16_rn(h);
                if (isL1 && t == Tc - 1) c1fin[(m0 + rl) * Hc + (u + nt * 4)] = creg[ci];
            }
        __syncthreads();
        if (tid < 256) {
            int rl = tid >> 1, half = tid & 1;
            *(uint4*)(hout + ((size_t)(m0 + rl) * Tc + t) * 512 + ut * 16 + half * 8) =
                *(const uint4*)(hst + rl * 16 + half * 8);
        }
        __syncthreads();
        if (tid == 0) red_release_add(&mycnt[mt], 1u);
    }
}

// ---------------- softmax + context (bf16 encoder history, ctx -> bf16 dab1) ----------------
__device__ __forceinline__ void softmax_ctx_one(
    int b, const float* __restrict__ energy, const __nv_bfloat16* __restrict__ hb1,
    __nv_bfloat16* __restrict__ dab1par, float (&sm)[Tc], float (&red)[256], int tid)
{
    float e0 = energy[b * Tc + tid];
    float e1 = energy[b * Tc + tid + 256];
    red[tid] = fmaxf(e0, e1);
    __syncthreads();
    for (int s = 128; s; s >>= 1) {
        if (tid < s) red[tid] = fmaxf(red[tid], red[tid + s]);
        __syncthreads();
    }
    float m = red[0];
    __syncthreads();
    float p0 = __expf(e0 - m), p1 = __expf(e1 - m);
    sm[tid] = p0; sm[tid + 256] = p1;
    red[tid] = p0 + p1;
    __syncthreads();
    for (int s = 128; s; s >>= 1) {
        if (tid < s) red[tid] += red[tid + s];
        __syncthreads();
    }
    float inv = __fdividef(1.0f, red[0]);
    __syncthreads();
    sm[tid] *= inv; sm[tid + 256] *= inv;
    __syncthreads();

    const __nv_bfloat16* base = hb1 + (size_t)b * Tc * 512 + tid * 2;
    float2 acc = make_float2(0.f, 0.f);
#pragma unroll 4
    for (int t = 0; t < Tc; ++t) {
        __nv_bfloat162 e = *(const __nv_bfloat162*)(base + (size_t)t * 512);
        float2 ef = __bfloat1622float2(e);
        float a = sm[t];
        acc.x += a * ef.x; acc.y += a * ef.y;
    }
    *(__nv_bfloat162*)(dab1par + (size_t)b * 1024 + tid * 2) = __float22bfloat162_rn(acc);
    __syncthreads();
}

// ---------------- persistent decoder (bf16 HMMA cells) ----------------
__global__ void __launch_bounds__(256) decoder_persistent(
    const __nv_bfloat16* __restrict__ hb1, const __nv_bfloat16* __restrict__ encprj,
    const float* __restrict__ c1,
    const __nv_bfloat16* __restrict__ attnWb, const float* __restrict__ attnv,
    const __nv_bfloat16* __restrict__ dW1b, const __nv_bfloat16* __restrict__ dW2b,
    const float* __restrict__ dwcolp2,
    const float* __restrict__ bD0p2, const float* __restrict__ bD1p2,
    const float* __restrict__ outW, const float* __restrict__ outb,
    __nv_bfloat16* __restrict__ dab1a, __nv_bfloat16* __restrict__ dab1b,
    __nv_bfloat16* __restrict__ dab2a, __nv_bfloat16* __restrict__ dab2b,
    float* __restrict__ hdf,
    float* __restrict__ cd0, float* __restrict__ cd1,
    float* __restrict__ decprj, float* __restrict__ energy,
    float* __restrict__ dinp, float* __restrict__ dout)
{
    __shared__ __align__(16) char sAc[64 * 128];     // 8KB
    __shared__ __align__(16) char sWc[128 * 128];    // 16KB
    __shared__ float sm[Tc];
    __shared__ float red[256];
    __shared__ float sdp[2][512];
    __shared__ float sv[512];
    const int tid = threadIdx.x, bid = blockIdx.x;
    const int warp = tid >> 5, lane = tid & 31;

    __nv_bfloat16* dab1[2] = { dab1a, dab1b };
    __nv_bfloat16* dab2[2] = { dab2a, dab2b };

    // init: h halves of parity-0 buffers, hdf, cd0
    for (int i = bid * 256 + tid; i < Bc * Hc; i += NBLK * 256) {
        int b = i >> 9, h = i & (Hc - 1);
        float v = __bfloat162float(hb1[((size_t)b * Tc + (Tc - 1)) * 512 + h]);
        hdf[i] = v;
        __nv_bfloat16 hv = __float2bfloat16_rn(v);
        dab1[0][(size_t)b * 1024 + 512 + h] = hv;
        dab2[0][(size_t)b * 1024 + 512 + h] = hv;
        cd0[i] = c1[i];
    }
    for (int i = tid; i < 512; i += 256) sv[i] = attnv[i];
    grid_sync();

    float* ccur = cd0; float* cnext = cd1;

    for (int s = 0; s < HOR; ++s) {
        const int par = s & 1;
        const __nv_bfloat16* d1 = dab1[par];
        const __nv_bfloat16* d2 = dab2[par];

        // P1: decproj = h @ attnWb^T  (bf16 HMMA, blocks 0..15, plain out fp32)
        if (bid < 16) {
            constexpr int MF = 4;
            float acc0[MF][4], acc1[MF][4];
#pragma unroll
            for (int i = 0; i < MF; ++i)
#pragma unroll
                for (int j = 0; j < 4; ++j) { acc0[i][j] = 0.f; acc1[i][j] = 0.f; }
            int m0 = (bid & 3) * 64, ny = bid >> 2;
            hmma_core<MF>(d1 + (size_t)m0 * 1024 + 512, 1024,
                          attnWb + (size_t)(ny * 128) * 512,
                          attnWb + (size_t)(ny * 128 + 64) * 512,
                          512, 8, acc0, acc1, sAc, sWc, tid, warp, lane);
            const int local = 2 * (warp * 4 + (lane & 3));
            const int r0 = lane >> 2;
#pragma unroll
            for (int mf = 0; mf < MF; ++mf) {
                int row = m0 + mf * 16 + r0;
                *(float2*)(decprj + (size_t)row * Hc + ny * 128 + local) =
                    make_float2(acc0[mf][0], acc0[mf][1]);
                *(float2*)(decprj + (size_t)(row + 8) * Hc + ny * 128 + local) =
                    make_float2(acc0[mf][2], acc0[mf][3]);
                *(float2*)(decprj + (size_t)row * Hc + ny * 128 + 64 + local) =
                    make_float2(acc1[mf][0], acc1[mf][1]);
                *(float2*)(decprj + (size_t)(row + 8) * Hc + ny * 128 + 64 + local) =
                    make_float2(acc1[mf][2], acc1[mf][3]);
            }
        }
        grid_sync();

        // P2: energy
        {
            for (int i = tid; i < 512; i += 256) {
                sdp[0][i] = decprj[(bid * 2) * Hc + i];
                sdp[1][i] = decprj[(bid * 2 + 1) * Hc + i];
            }
            __syncthreads();
            const float2* svf2 = (const float2*)sv;
            int row0 = bid * 1024 + warp * 128;
            for (int r = 0; r < 128; ++r) {
                int row = row0 + r;
                int local = (row >> 9) & 1;
                const __nv_bfloat162* ep2 = (const __nv_bfloat162*)(encprj + (size_t)row * Hc);
                const float2* dp2 = (const float2*)sdp[local];
                float part = 0.f;
#pragma unroll
                for (int i = 0; i < 8; ++i) {
                    int pidx = lane + 32 * i;
                    float2 ef = __bfloat1622float2(ep2[pidx]);
                    float2 df = dp2[pidx];
                    float2 vf = svf2[pidx];
                    part += tanh_hw(ef.x + df.x) * vf.x + tanh_hw(ef.y + df.y) * vf.y;
                }
#pragma unroll
                for (int o = 16; o; o >>= 1) part += __shfl_xor_sync(~0u, part, o);
                if (lane == 0) energy[row] = part;
            }
        }
        grid_sync();

        // P3: softmax + ctx (bf16 into dab1[par] cols 0-511)
        softmax_ctx_one(bid * 2 + 0, energy, hb1, dab1[par], sm, red, tid);
        softmax_ctx_one(bid * 2 + 1, energy, hb1, dab1[par], sm, red, tid);
        grid_sync();

        // P4: cell1 (bf16 HMMA, blocks 0..63): gates = [ctx|h] @ dW1b^T
        if (bid < 64) {
            constexpr int MF = 4;
            float aif[MF][4], ago[MF][4];
#pragma unroll
            for (int i = 0; i < MF; ++i)
#pragma unroll
                for (int j = 0; j < 4; ++j) { aif[i][j] = 0.f; ago[i][j] = 0.f; }
            int m0 = (bid & 3) * 64, ut = bid >> 2;
            hmma_core<MF>(d1 + (size_t)m0 * 1024, 1024,
                          dW1b + (size_t)(ut * 64) * 1024,
                          dW1b + (size_t)(1024 + ut * 64) * 1024,
                          1024, 16, aif, ago, sAc, sWc, tid, warp, lane);
            const int uo = warp * 4 + (lane & 3);         // unit within 32-tile
            const int u = ut * 32 + uo;
            const int np = ut * 64 + 2 * uo;              // pair index (if half)
            float2 bi  = *(const float2*)(bD0p2 + np);
            float2 bg  = *(const float2*)(bD0p2 + 1024 + np);
            float2 wci = *(const float2*)(dwcolp2 + np);
            float2 wcg = *(const float2*)(dwcolp2 + 1024 + np);
            const int r0 = lane >> 2;
            __nv_bfloat16* d2w = dab2[par];
#pragma unroll
            for (int mf = 0; mf < MF; ++mf) {
#pragma unroll
                for (int hh = 0; hh < 2; ++hh) {
                    int b = m0 + mf * 16 + r0 + hh * 8;
                    float sc = dinp[b];
                    float gi = aif[mf][2 * hh]     + bi.x + sc * wci.x;
                    float gf = aif[mf][2 * hh + 1] + bi.y + sc * wci.y;
                    float gg = ago[mf][2 * hh]     + bg.x + sc * wcg.x;
                    float go = ago[mf][2 * hh + 1] + bg.y + sc * wcg.y;
                    float cprev = ccur[b * Hc + u];
                    float cnew = sigf(gf) * cprev + sigf(gi) * tanhfast(gg);
                    float h0 = sigf(go) * tanhfast(cnew);
                    d2w[(size_t)b * 1024 + u] = __float2bfloat16_rn(h0);
                }
            }
        }
        grid_sync();

        // P5: cell2 (bf16 HMMA, blocks 0..63): gates = [h0|h] @ dW2b^T
        if (bid < 64) {
            constexpr int MF = 4;
            float aif[MF][4], ago[MF][4];
#pragma unroll
            for (int i = 0; i < MF; ++i)
#pragma unroll
                for (int j = 0; j < 4; ++j) { aif[i][j] = 0.f; ago[i][j] = 0.f; }
            int m0 = (bid & 3) * 64, ut = bid >> 2;
            hmma_core<MF>(d2 + (size_t)m0 * 1024, 1024,
                          dW2b + (size_t)(ut * 64) * 1024,
                          dW2b + (size_t)(1024 + ut * 64) * 1024,
                          1024, 16, aif, ago, sAc, sWc, tid, warp, lane);
            const int uo = warp * 4 + (lane & 3);
            const int u = ut * 32 + uo;
            const int np = ut * 64 + 2 * uo;
            float2 bi = *(const float2*)(bD1p2 + np);
            float2 bg = *(const float2*)(bD1p2 + 1024 + np);
            const int r0 = lane >> 2;
            __nv_bfloat16* n1 = dab1[1 - par];
            __nv_bfloat16* n2 = dab2[1 - par];
#pragma unroll
            for (int mf = 0; mf < MF; ++mf) {
#pragma unroll
                for (int hh = 0; hh < 2; ++hh) {
                    int b = m0 + mf * 16 + r0 + hh * 8;
                    float gi = aif[mf][2 * hh]     + bi.x;
                    float gf = aif[mf][2 * hh + 1] + bi.y;
                    float gg = ago[mf][2 * hh]     + bg.x;
                    float go = ago[mf][2 * hh + 1] + bg.y;
                    float cprev = ccur[b * Hc + u];
                    float cnew = sigf(gf) * cprev + sigf(gi) * tanhfast(gg);
                    float h = sigf(go) * tanhfast(cnew);
                    cnext[b * Hc + u] = cnew;
                    hdf[b * Hc + u] = h;
                    __nv_bfloat16 hv = __float2bfloat16_rn(h);
                    n1[(size_t)b * 1024 + 512 + u] = hv;
                    n2[(size_t)b * 1024 + 512 + u] = hv;
                }
            }
        }
        grid_sync();

        // P6: output projection + next dec input
        {
            int w = bid * 8 + warp;
            if (w < Bc * NQc) {
                int b = w / 3, q = w - b * 3;
                const float* hr = hdf + b * Hc;
                const float* wr = outW + q * Hc;
                float part = 0.f;
#pragma unroll
                for (int i = 0; i < 16; ++i) part += hr[lane + 32 * i] * wr[lane + 32 * i];
#pragma unroll
                for (int o = 16; o; o >>= 1) part += __shfl_xor_sync(~0u, part, o);
                if (lane == 0) {
                    float val = part + outb[q];
                    dout[(size_t)b * (HOR * NQc) + s * NQc + q] = val;
                    if (q == 1) dinp[b] = val;
                }
            }
        }
        grid_sync();

        float* tc = ccur; ccur = cnext; cnext = tc;
    }
}

// ---------------- host ----------------
template <typename T>
static T* sym_addr(const void* symbol) {
    void* p = nullptr;
    cudaGetSymbolAddress(&p, symbol);
    return (T*)p;
}

extern "C" void kernel_launch(void* const* d_in, const int* in_sizes, int n_in,
                              void* d_out, int out_size)
{
    const float* x      = (const float*)d_in[0];
    const float* eWih0  = (const float*)d_in[1];
    const float* eWhh0  = (const float*)d_in[2];
    const float* ebih0  = (const float*)d_in[3];
    const float* ebhh0  = (const float*)d_in[4];
    const float* eWih1  = (const float*)d_in[5];
    const float* eWhh1  = (const float*)d_in[6];
    const float* ebih1  = (const float*)d_in[7];
    const float* ebhh1  = (const float*)d_in[8];
    const float* dWih0  = (const float*)d_in[9];
    const float* dWhh0  = (const float*)d_in[10];
    const float* dbih0  = (const float*)d_in[11];
    const float* dbhh0  = (const float*)d_in[12];
    const float* dWih1  = (const float*)d_in[13];
    const float* dWhh1  = (const float*)d_in[14];
    const float* dbih1  = (const float*)d_in[15];
    const float* dbhh1  = (const float*)d_in[16];
    const float* attnW  = (const float*)d_in[17];
    const float* attnv  = (const float*)d_in[18];
    const float* outW   = (const float*)d_in[19];
    const float* outb   = (const float*)d_in[20];
    float* dout = (float*)d_out;

    float* pre    = sym_addr<float>(g_pre);
    __nv_bfloat16* xb    = sym_addr<__nv_bfloat16>(g_xb);
    __nv_bfloat16* hb0   = sym_addr<__nv_bfloat16>(g_hb0);
    __nv_bfloat16* hb1   = sym_addr<__nv_bfloat16>(g_hb1);
    __nv_bfloat16* Wih0b = sym_addr<__nv_bfloat16>(g_Wih0b);
    __nv_bfloat16* Whh0b = sym_addr<__nv_bfloat16>(g_Whh0b);
    __nv_bfloat16* Wih1b = sym_addr<__nv_bfloat16>(g_Wih1b);
    __nv_bfloat16* Whh1b = sym_addr<__nv_bfloat16>(g_Whh1b);
    __nv_bfloat16* attnWb = sym_addr<__nv_bfloat16>(g_attnWb);
    __nv_bfloat16* encprj = sym_addr<__nv_bfloat16>(g_encproj);
    __nv_bfloat16* dW1b  = sym_addr<__nv_bfloat16>(g_dW1b);
    __nv_bfloat16* dW2b  = sym_addr<__nv_bfloat16>(g_dW2b);
    __nv_bfloat16* dab1a = sym_addr<__nv_bfloat16>(g_dab1);
    __nv_bfloat16* dab1b = dab1a + (size_t)Bc * 1024;
    __nv_bfloat16* dab2a = sym_addr<__nv_bfloat16>(g_dab2);
    __nv_bfloat16* dab2b = dab2a + (size_t)Bc * 1024;
    float* bE0    = sym_addr<float>(g_bE0p2);
    float* bE1    = sym_addr<float>(g_bE1p2);
    float* bD0p2  = sym_addr<float>(g_bD0p2);
    float* bD1p2  = sym_addr<float>(g_bD1p2);
    float* dwcolp2 = sym_addr<float>(g_dwcol0p2);
    float* c1     = sym_addr<float>(g_c1);
    float* hdf    = sym_addr<float>(g_hdf);
    float* cd0    = sym_addr<float>(g_cd0);
    float* cd1    = sym_addr<float>(g_cd1);
    float* decprj = sym_addr<float>(g_decproj);
    float* energy = sym_addr<float>(g_energy);
    float* dinp   = sym_addr<float>(g_dinp);
    unsigned* cntA = sym_addr<unsigned>(g_cntA);
    unsigned* cntB = sym_addr<unsigned>(g_cntB);

    constexpr int ENC_SMEM = 16 * 8192 + 4 * 16384;   // 192KB
    cudaFuncSetAttribute(enc_overlap, cudaFuncAttributeMaxDynamicSharedMemorySize, ENC_SMEM);

    // 0) prep
    prep_kernel<<<(Bc * Tc * Ic + 255) / 256, 256>>>(
        x, eWih0, eWhh0, ebih0, ebhh0, eWih1, eWhh1, ebih1, ebhh1,
        dWih0, dWhh0, dbih0, dbhh0, dWih1, dWhh1, dbih1, dbhh1, attnW);

    // 1) P0 = xb @ Wih0b^T
    gemm_bf16pair<<<dim3(Bc * Tc / 64, 16), 256>>>(xb, Ic, Wih0b, Ic, Ic, pre, Gc);

    // 2) overlapped dual-layer encoder
    enc_overlap<<<NBLK, 512, ENC_SMEM>>>(
        hb0, hb1, Whh0b, Wih1b, Whh1b, pre, bE0, bE1, cntA, cntB, c1);

    // 3) enc_proj = hb1 @ attnWb^T
    gemm_bf16pb<<<dim3(Bc * Tc / 64, 4), 256>>>(hb1, Hc, attnWb, Hc, Hc, encprj, Hc);

    // 4) decoder (bf16 HMMA cells)
    decoder_persistent<<<NBLK, 256>>>(
        hb1, encprj, c1, attnWb, attnv,
        dW1b, dW2b, dwcolp2, bD0p2, bD1p2, outW, outb,
        dab1a, dab1b, dab2a, dab2b, hdf, cd0, cd1,
        decprj, energy, dinp, dout);
}